// round 7
// baseline (speedup 1.0000x reference)
#include <cuda_runtime.h>
#include <math.h>

// ---------------- problem constants ----------------
#define TT 2048
#define DD 1024
#define TG 256      // global tokens (stride 8)

// ---------------- one scratch block; head-grouped S keeps total < 160 MB ----------------
constexpr long long SZ_S     = 4LL * 2048 * 2048;   // 4 heads per group
constexpr long long SZ_STATS = 16LL * 2048 * 2;
constexpr long long SZ_MAT   = 2048LL * 1024;
constexpr long long SZ_HIN   = 2048LL * 2048;
constexpr long long SZ_G     = 256LL * 1024;
constexpr long long SZ_RT    = 16LL * 64 * 64;

constexpr long long OFF_S      = 0;
constexpr long long OFF_STATS  = OFF_S + SZ_S;
constexpr long long OFF_Q      = OFF_STATS + SZ_STATS;
constexpr long long OFF_K      = OFF_Q + SZ_MAT;
constexpr long long OFF_V      = OFF_K + SZ_MAT;
constexpr long long OFF_AO     = OFF_V + SZ_MAT;
constexpr long long OFF_LIN    = OFF_AO + SZ_MAT;
constexpr long long OFF_SP     = OFF_LIN + SZ_MAT;
constexpr long long OFF_QT     = OFF_SP + SZ_MAT;
constexpr long long OFF_HIN    = OFF_QT + SZ_MAT;
constexpr long long OFF_HOUT   = OFF_HIN + SZ_HIN;
constexpr long long OFF_GQ     = OFF_HOUT + SZ_MAT;
constexpr long long OFF_GK     = OFF_GQ + SZ_G;
constexpr long long OFF_GV     = OFF_GK + SZ_G;
constexpr long long OFF_GAO    = OFF_GV + SZ_G;
constexpr long long OFF_GSM    = OFF_GAO + SZ_G;
constexpr long long OFF_RT     = OFF_GSM + SZ_G;
constexpr long long OFF_SCALES = OFF_RT + SZ_RT;
constexpr long long SCRATCH_TOTAL = OFF_SCALES + 64;   // ~39.2M floats = 157 MB

__device__ float g_scratch[SCRATCH_TOTAL];

// ---------------- prep: transpose R_quant, build per-head score scales ----------------
__global__ void prep_kernel(const float* __restrict__ R, const float* __restrict__ spars,
                            const float* __restrict__ ent) {
    float* Rt = g_scratch + OFF_RT;
    float* scales = g_scratch + OFF_SCALES;
    int idx = blockIdx.x * 256 + threadIdx.x;
    if (idx < 16 * 64 * 64) {
        int h = idx >> 12, rem = idx & 4095;
        int d = rem >> 6, e = rem & 63;
        Rt[h * 4096 + e * 64 + d] = R[h * 4096 + d * 64 + e];
    }
    if (idx < 16) {
        scales[idx] = 0.125f;                                   // 1/sqrt(64)
        scales[16 + idx] = (spars[idx] > 0.0f) ? 0.125f : 0.0f; // sigmoid(x)>0.5 <=> x>0
        float g = 1.0f / (1.0f + __expf(-ent[idx * 4]));        // ent_gate[h,0,0]
        scales[32 + idx] = g * 0.125f;
    }
    if (idx < 8) scales[48 + idx] = 0.08838834764831845f;       // 1/sqrt(128)
}

// ---------------- generic tiled GEMM: C[z] = scale[z] * A[z] @ B[z]^T + bias ----------------
#define BM 64
#define BN 64
#define BK 16
__global__ void __launch_bounds__(256) gemm_abt(
    const float* __restrict__ Aext, long long aOff, long long aStride, int lda,
    const float* __restrict__ Bext, long long bOff, long long bStride, int ldb,
    const float* __restrict__ bias,
    long long scaleOff,
    long long cOff, long long cStride, int ldc,
    int M, int N, int K) {
    int z = blockIdx.z;
    const float* A = (Aext ? Aext : g_scratch + aOff) + z * aStride;
    const float* B = (Bext ? Bext : g_scratch + bOff) + z * bStride;
    float* C = g_scratch + cOff + z * cStride;
    float scale = (scaleOff >= 0) ? g_scratch[scaleOff + z] : 1.0f;
    int m0 = blockIdx.y * BM, n0 = blockIdx.x * BN;
    __shared__ float As[BK][BM + 4];
    __shared__ float Bs[BK][BN + 4];
    int tid = threadIdx.x;
    int lr = tid >> 2;            // 0..63 row within tile
    int lk = (tid & 3) << 2;      // 0,4,8,12
    int ty = tid >> 4, tx = tid & 15;
    float acc[4][4] = {};
    for (int k0 = 0; k0 < K; k0 += BK) {
        float4 a4 = *(const float4*)(A + (long long)(m0 + lr) * lda + k0 + lk);
        float4 b4 = *(const float4*)(B + (long long)(n0 + lr) * ldb + k0 + lk);
        As[lk + 0][lr] = a4.x; As[lk + 1][lr] = a4.y; As[lk + 2][lr] = a4.z; As[lk + 3][lr] = a4.w;
        Bs[lk + 0][lr] = b4.x; Bs[lk + 1][lr] = b4.y; Bs[lk + 2][lr] = b4.z; Bs[lk + 3][lr] = b4.w;
        __syncthreads();
#pragma unroll
        for (int kk = 0; kk < BK; kk++) {
            float4 av = *(const float4*)&As[kk][ty * 4];
            float4 bv = *(const float4*)&Bs[kk][tx * 4];
            acc[0][0] += av.x * bv.x; acc[0][1] += av.x * bv.y; acc[0][2] += av.x * bv.z; acc[0][3] += av.x * bv.w;
            acc[1][0] += av.y * bv.x; acc[1][1] += av.y * bv.y; acc[1][2] += av.y * bv.z; acc[1][3] += av.y * bv.w;
            acc[2][0] += av.z * bv.x; acc[2][1] += av.z * bv.y; acc[2][2] += av.z * bv.z; acc[2][3] += av.z * bv.w;
            acc[3][0] += av.w * bv.x; acc[3][1] += av.w * bv.y; acc[3][2] += av.w * bv.z; acc[3][3] += av.w * bv.w;
        }
        __syncthreads();
    }
#pragma unroll
    for (int i = 0; i < 4; i++) {
#pragma unroll
        for (int j = 0; j < 4; j++) {
            float v = acc[i][j] * scale;
            if (bias) v += bias[n0 + tx * 4 + j];
            C[(long long)(m0 + ty * 4 + i) * ldc + n0 + tx * 4 + j] = v;
        }
    }
}

// ---------------- softmax row stats: max + 1/sum(exp) per (head,row) ----------------
__global__ void stats_kernel(long long sOff, long long statsOff, int Ts) {
    int h = blockIdx.y, t = blockIdx.x;
    const float* row = g_scratch + sOff + ((long long)h * Ts + t) * Ts;
    float* stats = g_scratch + statsOff;
    __shared__ float red[256];
    int tid = threadIdx.x;
    float m = -1e30f;
    for (int s = tid; s < Ts; s += 256) m = fmaxf(m, row[s]);
    red[tid] = m; __syncthreads();
    for (int st = 128; st > 0; st >>= 1) {
        if (tid < st) red[tid] = fmaxf(red[tid], red[tid + st]);
        __syncthreads();
    }
    m = red[0]; __syncthreads();
    float sum = 0.0f;
    for (int s = tid; s < Ts; s += 256) sum += __expf(row[s] - m);
    red[tid] = sum; __syncthreads();
    for (int st = 128; st > 0; st >>= 1) {
        if (tid < st) red[tid] += red[tid + st];
        __syncthreads();
    }
    if (tid == 0) {
        stats[((long long)h * Ts + t) * 2] = m;
        stats[((long long)h * Ts + t) * 2 + 1] = 1.0f / red[0];
    }
}

// ---------------- AV: O[t, h*HDv + d] = sum_s softmax(S)[t,s] * V[s, h*HDv + d] ----------------
template <int HDv, int SB>
__global__ void __launch_bounds__(256) av_kernel(
    long long sOff, long long statsOff,
    const float* __restrict__ Vext, long long vOff, int vrs,
    long long oOff, int ors, int Ts) {
    int h = blockIdx.y;
    int t0 = blockIdx.x * 64;
    const float* V = Vext ? Vext : g_scratch + vOff;
    float* O = g_scratch + oOff;
    const float* Sp = g_scratch + sOff + ((long long)h * Ts + t0) * Ts;
    const float* st = g_scratch + statsOff + ((long long)h * Ts + t0) * 2;
    __shared__ float Ps[64][SB + 4];
    __shared__ float Vs[SB][HDv];
    __shared__ float smx[64], srd[64];
    int tid = threadIdx.x;
    if (tid < 64) { smx[tid] = st[tid * 2]; srd[tid] = st[tid * 2 + 1]; }
    __syncthreads();
    constexpr int NJ = HDv / 16;
    float acc[4][NJ] = {};
    int ty = tid >> 4, tx = tid & 15;
    int pr = tid >> 2, pc0 = (tid & 3) * (SB / 4);
    constexpr int TPRV = 256 / SB;
    int vr = tid / TPRV, vc0 = (tid % TPRV) * (HDv / TPRV);
    for (int s0 = 0; s0 < Ts; s0 += SB) {
        float m = smx[pr], r = srd[pr];
#pragma unroll
        for (int c = 0; c < SB / 4; c += 4) {
            float4 sv = *(const float4*)(Sp + (long long)pr * Ts + s0 + pc0 + c);
            Ps[pr][pc0 + c + 0] = __expf(sv.x - m) * r;
            Ps[pr][pc0 + c + 1] = __expf(sv.y - m) * r;
            Ps[pr][pc0 + c + 2] = __expf(sv.z - m) * r;
            Ps[pr][pc0 + c + 3] = __expf(sv.w - m) * r;
        }
#pragma unroll
        for (int c = 0; c < HDv / TPRV; c += 4) {
            float4 vv = *(const float4*)(V + (long long)(s0 + vr) * vrs + h * HDv + vc0 + c);
            Vs[vr][vc0 + c + 0] = vv.x; Vs[vr][vc0 + c + 1] = vv.y;
            Vs[vr][vc0 + c + 2] = vv.z; Vs[vr][vc0 + c + 3] = vv.w;
        }
        __syncthreads();
#pragma unroll 8
        for (int s = 0; s < SB; s++) {
            float pv[4];
#pragma unroll
            for (int i = 0; i < 4; i++) pv[i] = Ps[ty * 4 + i][s];
#pragma unroll
            for (int j = 0; j < NJ; j++) {
                float vv = Vs[s][tx * NJ + j];
#pragma unroll
                for (int i = 0; i < 4; i++) acc[i][j] += pv[i] * vv;
            }
        }
        __syncthreads();
    }
#pragma unroll
    for (int i = 0; i < 4; i++)
#pragma unroll
        for (int j = 0; j < NJ; j++)
            O[(long long)(t0 + ty * 4 + i) * ors + h * HDv + tx * NJ + j] = acc[i][j];
}

// ---------------- combined slice j: out_j += c/16 * sum_{h<4} softmax(S)[h,t,s] ----------------
// c = sp[0] + sp[1] + sp[3]  (broadcast quirk in the reference: every slice gets the same scalar)
__global__ void __launch_bounds__(256) combined_add(
    long long sOff, long long statsOff,
    const float* __restrict__ sp, float* __restrict__ out, int accumulate) {
    int t0 = blockIdx.y * 64, s0 = blockIdx.x * 64;
    const float* stats = g_scratch + statsOff;
    __shared__ float smx[4][64], srd[4][64];
    int tid = threadIdx.x;
    {
        int hh = tid >> 6, t = tid & 63;   // 256 threads = 4*64 exactly
        smx[hh][t] = stats[((long long)hh * TT + t0 + t) * 2];
        srd[hh][t] = stats[((long long)hh * TT + t0 + t) * 2 + 1];
    }
    __syncthreads();
    int ty = tid >> 4, tx = tid & 15;
    float acc[4][4] = {};
    for (int h = 0; h < 4; h++) {
        const float* Sp = g_scratch + sOff + ((long long)h * TT + t0) * TT + s0;
#pragma unroll
        for (int i = 0; i < 4; i++) {
            int t = ty * 4 + i;
            float m = smx[h][t], r = srd[h][t];
            float4 sv = *(const float4*)(Sp + (long long)t * TT + tx * 4);
            acc[i][0] += __expf(sv.x - m) * r;
            acc[i][1] += __expf(sv.y - m) * r;
            acc[i][2] += __expf(sv.z - m) * r;
            acc[i][3] += __expf(sv.w - m) * r;
        }
    }
    float coeff = (sp[0] + sp[1] + sp[3]) * (1.0f / 16.0f);
#pragma unroll
    for (int i = 0; i < 4; i++)
#pragma unroll
        for (int j = 0; j < 4; j++) {
            long long o = (long long)(t0 + ty * 4 + i) * TT + s0 + tx * 4 + j;
            float v = coeff * acc[i][j];
            if (accumulate) v += out[o];
            out[o] = v;
        }
}

// ---------------- linear interpolation of g_small [256,1024] -> hier_in[:,1024:2048] ----------------
__global__ void interp_kernel(long long gsOff, long long hinOff) {
    const float* gsmall = g_scratch + gsOff;
    float* hin = g_scratch + hinOff;
    int idx = blockIdx.x * 256 + threadIdx.x;
    if (idx >= TT * DD) return;
    int t = idx >> 10, c = idx & 1023;
    float src = (t + 0.5f) * (256.0f / 2048.0f) - 0.5f;
    src = fminf(fmaxf(src, 0.0f), 255.0f);
    int i0 = (int)floorf(src);
    int i1 = min(i0 + 1, 255);
    float w = src - (float)i0;
    hin[(long long)t * 2048 + 1024 + c] = gsmall[i0 * 1024 + c] * (1.0f - w) + gsmall[i1 * 1024 + c] * w;
}

// ---------------- weighted = p0*lin + p1*sparse + p2*hier + p3*quantum ----------------
__global__ void weighted_kernel(const float* __restrict__ sp,
                                long long aOff, long long bOff, long long cOff, long long dOff,
                                float* __restrict__ out) {
    int idx = blockIdx.x * 256 + threadIdx.x;
    if (idx >= TT * DD) return;
    out[idx] = sp[0] * g_scratch[aOff + idx] + sp[1] * g_scratch[bOff + idx]
             + sp[2] * g_scratch[cOff + idx] + sp[3] * g_scratch[dOff + idx];
}

// ---------------- host launcher: kernel launches ONLY ----------------
extern "C" void kernel_launch(void* const* d_in, const int* in_sizes, int n_in,
                              void* d_out, int out_size) {
    const float* query = (const float*)d_in[0];
    const float* key   = (const float*)d_in[1];
    const float* value = (const float*)d_in[2];
    const float* sp    = (const float*)d_in[3];
    const float* Wqkv_lin = (const float*)d_in[4];
    const float* b_lin  = (const float*)d_in[5];
    const float* Wo_lin = (const float*)d_in[6];
    const float* bo_lin = (const float*)d_in[7];
    const float* spars  = (const float*)d_in[8];
    const float* Wqkv_loc = (const float*)d_in[9];
    const float* b_loc  = (const float*)d_in[10];
    const float* Wo_loc = (const float*)d_in[11];
    const float* bo_loc = (const float*)d_in[12];
    const float* Wqkv_glb = (const float*)d_in[13];
    const float* b_glb  = (const float*)d_in[14];
    const float* Wo_glb = (const float*)d_in[15];
    const float* bo_glb = (const float*)d_in[16];
    const float* Wf = (const float*)d_in[17];
    const float* bf = (const float*)d_in[18];
    const float* Rq = (const float*)d_in[19];
    const float* ent = (const float*)d_in[20];

    float* out = (float*)d_out;
    // combined is (3, T, T): slice j at out + T*D + j*T*T
    float* comb0 = out + (size_t)TT * DD;                       // linear_w
    float* comb1 = comb0 + (size_t)TT * TT;                     // sparse_w
    float* comb2 = comb1 + (size_t)TT * TT;                     // quantum_w

    const long long TT2 = (long long)TT * TT;

    prep_kernel<<<256, 256>>>(Rq, spars, ent);

    dim3 gProj(16, 32, 1);      // N=1024, M=2048
    dim3 gScores4(32, 32, 4);   // T x T, 4 heads per group
    dim3 gComb(32, 32);

    // ===== Linear MHA (4 head-groups of 4) =====
    gemm_abt<<<gProj, 256>>>(query, 0, 0, DD, Wqkv_lin, 0, 0, DD, b_lin, -1, OFF_Q, 0, DD, TT, DD, DD);
    gemm_abt<<<gProj, 256>>>(key,   0, 0, DD, Wqkv_lin + DD * DD, 0, 0, DD, b_lin + DD, -1, OFF_K, 0, DD, TT, DD, DD);
    gemm_abt<<<gProj, 256>>>(value, 0, 0, DD, Wqkv_lin + 2 * DD * DD, 0, 0, DD, b_lin + 2 * DD, -1, OFF_V, 0, DD, TT, DD, DD);
    for (int g = 0; g < 4; g++) {
        long long ho = (long long)g * 256;   // 4 heads * 64 dims
        gemm_abt<<<gScores4, 256>>>(nullptr, OFF_Q + ho, 64, DD, nullptr, OFF_K + ho, 64, DD, nullptr, OFF_SCALES + g * 4, OFF_S, TT2, TT, TT, TT, 64);
        stats_kernel<<<dim3(TT, 4), 256>>>(OFF_S, OFF_STATS, TT);
        av_kernel<64, 64><<<dim3(32, 4), 256>>>(OFF_S, OFF_STATS, nullptr, OFF_V + ho, DD, OFF_AO + ho, DD, TT);
        combined_add<<<gComb, 256>>>(OFF_S, OFF_STATS, sp, comb0, g == 0 ? 0 : 1);
    }
    gemm_abt<<<gProj, 256>>>(nullptr, OFF_AO, 0, DD, Wo_lin, 0, 0, DD, bo_lin, -1, OFF_LIN, 0, DD, TT, DD, DD);

    // ===== Sparse (raw heads, masked scale) =====
    for (int g = 0; g < 4; g++) {
        long long ho = (long long)g * 256;
        gemm_abt<<<gScores4, 256>>>(query + ho, 0, 64, DD, key + ho, 0, 64, DD, nullptr, OFF_SCALES + 16 + g * 4, OFF_S, TT2, TT, TT, TT, 64);
        stats_kernel<<<dim3(TT, 4), 256>>>(OFF_S, OFF_STATS, TT);
        av_kernel<64, 64><<<dim3(32, 4), 256>>>(OFF_S, OFF_STATS, value + ho, 0, DD, OFF_SP + ho, DD, TT);
        combined_add<<<gComb, 256>>>(OFF_S, OFF_STATS, sp, comb1, g == 0 ? 0 : 1);
    }

    // ===== Quantum (rotated heads, gated scale) =====
    gemm_abt<<<dim3(1, 32, 16), 256>>>(query, 0, 64, DD, nullptr, OFF_RT, 4096, 64, nullptr, -1, OFF_Q, 64, DD, TT, 64, 64);
    gemm_abt<<<dim3(1, 32, 16), 256>>>(key,   0, 64, DD, nullptr, OFF_RT, 4096, 64, nullptr, -1, OFF_K, 64, DD, TT, 64, 64);
    for (int g = 0; g < 4; g++) {
        long long ho = (long long)g * 256;
        gemm_abt<<<gScores4, 256>>>(nullptr, OFF_Q + ho, 64, DD, nullptr, OFF_K + ho, 64, DD, nullptr, OFF_SCALES + 32 + g * 4, OFF_S, TT2, TT, TT, TT, 64);
        stats_kernel<<<dim3(TT, 4), 256>>>(OFF_S, OFF_STATS, TT);
        av_kernel<64, 64><<<dim3(32, 4), 256>>>(OFF_S, OFF_STATS, value + ho, 0, DD, OFF_QT + ho, DD, TT);
        combined_add<<<gComb, 256>>>(OFF_S, OFF_STATS, sp, comb2, g == 0 ? 0 : 1);
    }

    // ===== Local MHA (8 heads of 128, 2 groups of 4) =====
    gemm_abt<<<gProj, 256>>>(query, 0, 0, DD, Wqkv_loc, 0, 0, DD, b_loc, -1, OFF_Q, 0, DD, TT, DD, DD);
    gemm_abt<<<gProj, 256>>>(key,   0, 0, DD, Wqkv_loc + DD * DD, 0, 0, DD, b_loc + DD, -1, OFF_K, 0, DD, TT, DD, DD);
    gemm_abt<<<gProj, 256>>>(value, 0, 0, DD, Wqkv_loc + 2 * DD * DD, 0, 0, DD, b_loc + 2 * DD, -1, OFF_V, 0, DD, TT, DD, DD);
    for (int g = 0; g < 2; g++) {
        long long ho = (long long)g * 512;   // 4 heads * 128 dims
        gemm_abt<<<gScores4, 256>>>(nullptr, OFF_Q + ho, 128, DD, nullptr, OFF_K + ho, 128, DD, nullptr, OFF_SCALES + 48 + g * 4, OFF_S, TT2, TT, TT, TT, 128);
        stats_kernel<<<dim3(TT, 4), 256>>>(OFF_S, OFF_STATS, TT);
        av_kernel<128, 32><<<dim3(32, 4), 256>>>(OFF_S, OFF_STATS, nullptr, OFF_V + ho, DD, OFF_AO + ho, DD, TT);
    }
    gemm_abt<<<gProj, 256>>>(nullptr, OFF_AO, 0, DD, Wo_loc, 0, 0, DD, bo_loc, -1, OFF_HIN, 0, 2048, TT, DD, DD);

    // ===== Global MHA (subsampled tokens stride 8, 8 heads of 128) =====
    dim3 gProjG(16, 4, 1);  // M=256
    gemm_abt<<<gProjG, 256>>>(query, 0, 0, 8 * DD, Wqkv_glb, 0, 0, DD, b_glb, -1, OFF_GQ, 0, DD, TG, DD, DD);
    gemm_abt<<<gProjG, 256>>>(key,   0, 0, 8 * DD, Wqkv_glb + DD * DD, 0, 0, DD, b_glb + DD, -1, OFF_GK, 0, DD, TG, DD, DD);
    gemm_abt<<<gProjG, 256>>>(value, 0, 0, 8 * DD, Wqkv_glb + 2 * DD * DD, 0, 0, DD, b_glb + 2 * DD, -1, OFF_GV, 0, DD, TG, DD, DD);
    gemm_abt<<<dim3(4, 4, 8), 256>>>(nullptr, OFF_GQ, 128, DD, nullptr, OFF_GK, 128, DD, nullptr, OFF_SCALES + 48, OFF_S, (long long)TG * TG, TG, TG, TG, 128);
    stats_kernel<<<dim3(TG, 8), 256>>>(OFF_S, OFF_STATS, TG);
    av_kernel<128, 32><<<dim3(4, 8), 256>>>(OFF_S, OFF_STATS, nullptr, OFF_GV, DD, OFF_GAO, DD, TG);
    gemm_abt<<<gProjG, 256>>>(nullptr, OFF_GAO, 0, DD, Wo_glb, 0, 0, DD, bo_glb, -1, OFF_GSM, 0, DD, TG, DD, DD);
    interp_kernel<<<(TT * DD + 255) / 256, 256>>>(OFF_GSM, OFF_HIN);

    // ===== Hierarchical fuse: [local|global] @ Wf^T + bf =====
    gemm_abt<<<gProj, 256>>>(nullptr, OFF_HIN, 0, 2048, Wf, 0, 0, 2048, bf, -1, OFF_HOUT, 0, DD, TT, DD, 2048);

    // ===== Weighted combination =====
    weighted_kernel<<<(TT * DD + 255) / 256, 256>>>(sp, OFF_LIN, OFF_SP, OFF_HOUT, OFF_QT, out);
}

// round 10
// speedup vs baseline: 1.5630x; 1.5630x over previous
#include <cuda_runtime.h>
#include <math.h>

// ---------------- problem constants ----------------
#define TT 2048
#define DD 1024
#define TG 256      // global tokens (stride 8)

// ---------------- one scratch block; head-grouped S keeps total < 160 MB ----------------
constexpr long long SZ_S     = 4LL * 2048 * 2048;   // 4 heads per group
constexpr long long SZ_STATS = 16LL * 2048 * 2;
constexpr long long SZ_MAT   = 2048LL * 1024;
constexpr long long SZ_HIN   = 2048LL * 2048;
constexpr long long SZ_G     = 256LL * 1024;
constexpr long long SZ_RT    = 16LL * 64 * 64;

constexpr long long OFF_S      = 0;
constexpr long long OFF_STATS  = OFF_S + SZ_S;
constexpr long long OFF_Q      = OFF_STATS + SZ_STATS;
constexpr long long OFF_K      = OFF_Q + SZ_MAT;
constexpr long long OFF_V      = OFF_K + SZ_MAT;
constexpr long long OFF_AO     = OFF_V + SZ_MAT;
constexpr long long OFF_LIN    = OFF_AO + SZ_MAT;
constexpr long long OFF_SP     = OFF_LIN + SZ_MAT;
constexpr long long OFF_QT     = OFF_SP + SZ_MAT;
constexpr long long OFF_HIN    = OFF_QT + SZ_MAT;
constexpr long long OFF_HOUT   = OFF_HIN + SZ_HIN;
constexpr long long OFF_GQ     = OFF_HOUT + SZ_MAT;
constexpr long long OFF_GK     = OFF_GQ + SZ_G;
constexpr long long OFF_GV     = OFF_GK + SZ_G;
constexpr long long OFF_GAO    = OFF_GV + SZ_G;
constexpr long long OFF_GSM    = OFF_GAO + SZ_G;
constexpr long long OFF_RT     = OFF_GSM + SZ_G;
constexpr long long OFF_SCALES = OFF_RT + SZ_RT;
constexpr long long SCRATCH_TOTAL = OFF_SCALES + 64;   // ~39.2M floats = 157 MB

__device__ float g_scratch[SCRATCH_TOTAL];

// ---------------- tf32 helpers ----------------
__device__ __forceinline__ unsigned f2tf(float f) {
    unsigned u;
    asm("cvt.rna.tf32.f32 %0, %1;" : "=r"(u) : "f"(f));
    return u;
}
// 3xTF32 split: x ~= hi + lo, each representable in tf32
__device__ __forceinline__ void split_tf32(float x, unsigned& hi, unsigned& lo) {
    hi = f2tf(x);
    lo = f2tf(x - __uint_as_float(hi));
}
__device__ __forceinline__ void mma_tf32(float* d, const unsigned* a, const unsigned* b) {
    asm volatile(
        "mma.sync.aligned.m16n8k8.row.col.f32.tf32.tf32.f32 "
        "{%0,%1,%2,%3}, {%4,%5,%6,%7}, {%8,%9}, {%0,%1,%2,%3};"
        : "+f"(d[0]), "+f"(d[1]), "+f"(d[2]), "+f"(d[3])
        : "r"(a[0]), "r"(a[1]), "r"(a[2]), "r"(a[3]), "r"(b[0]), "r"(b[1]));
}

// ---------------- prep: transpose R_quant, build per-head score scales ----------------
__global__ void prep_kernel(const float* __restrict__ R, const float* __restrict__ spars,
                            const float* __restrict__ ent) {
    float* Rt = g_scratch + OFF_RT;
    float* scales = g_scratch + OFF_SCALES;
    int idx = blockIdx.x * 256 + threadIdx.x;
    if (idx < 16 * 64 * 64) {
        int h = idx >> 12, rem = idx & 4095;
        int d = rem >> 6, e = rem & 63;
        Rt[h * 4096 + e * 64 + d] = R[h * 4096 + d * 64 + e];
    }
    if (idx < 16) {
        scales[idx] = 0.125f;                                   // 1/sqrt(64)
        scales[16 + idx] = (spars[idx] > 0.0f) ? 0.125f : 0.0f; // sigmoid(x)>0.5 <=> x>0
        float g = 1.0f / (1.0f + __expf(-ent[idx * 4]));        // ent_gate[h,0,0]
        scales[32 + idx] = g * 0.125f;
    }
    if (idx < 8) scales[48 + idx] = 0.08838834764831845f;       // 1/sqrt(128)
}

// ---------------- 3xTF32 tensor-core GEMM: C[z] = scale[z] * A[z] @ B[z]^T + bias ----------------
// CTA tile 128x64, BK=16, 8 warps of 32x32. Single-buffered smem (hi+lo), register prefetch.
// Requires: M % 128 == 0, N % 64 == 0, K % 16 == 0 (all call sites satisfy this).
__global__ void __launch_bounds__(256) gemm_tf32(
    const float* __restrict__ Aext, long long aOff, long long aStride, int lda,
    const float* __restrict__ Bext, long long bOff, long long bStride, int ldb,
    const float* __restrict__ bias,
    long long scaleOff,
    long long cOff, long long cStride, int ldc,
    int M, int N, int K) {
    int z = blockIdx.z;
    const float* A = (Aext ? Aext : g_scratch + aOff) + z * aStride;
    const float* B = (Bext ? Bext : g_scratch + bOff) + z * bStride;
    float* C = g_scratch + cOff + z * cStride;
    float scale = (scaleOff >= 0) ? g_scratch[scaleOff + z] : 1.0f;
    int m0 = blockIdx.y * 128, n0 = blockIdx.x * 64;

    __shared__ unsigned Ah[16][132], Al[16][132];   // [k][m]
    __shared__ unsigned Bh[16][68],  Bl[16][68];    // [k][n]

    int tid = threadIdx.x, lane = tid & 31, wp = tid >> 5;
    int g = lane >> 2, tig = lane & 3;
    int wr = wp >> 1, wc = wp & 1;
    int mw = wr * 32, nw = wc * 32;

    float acc[2][4][4];
#pragma unroll
    for (int a = 0; a < 2; a++)
#pragma unroll
        for (int b = 0; b < 4; b++)
#pragma unroll
            for (int c = 0; c < 4; c++) acc[a][b][c] = 0.0f;

    int arow = tid >> 2, akq = (tid & 3) << 2;
    const float* Ap1 = A + (long long)(m0 + arow) * lda + akq;
    const float* Ap2 = A + (long long)(m0 + arow + 64) * lda + akq;
    const float* Bp  = B + (long long)(n0 + arow) * ldb + akq;

    int nk = K >> 4;
    float4 ra1 = *(const float4*)(Ap1);
    float4 ra2 = *(const float4*)(Ap2);
    float4 rb  = *(const float4*)(Bp);

    // write splits into smem
    auto store_tiles = [&](const float4& a1, const float4& a2, const float4& b) {
        unsigned h, l;
        split_tf32(a1.x, h, l); Ah[akq + 0][arow] = h; Al[akq + 0][arow] = l;
        split_tf32(a1.y, h, l); Ah[akq + 1][arow] = h; Al[akq + 1][arow] = l;
        split_tf32(a1.z, h, l); Ah[akq + 2][arow] = h; Al[akq + 2][arow] = l;
        split_tf32(a1.w, h, l); Ah[akq + 3][arow] = h; Al[akq + 3][arow] = l;
        split_tf32(a2.x, h, l); Ah[akq + 0][arow + 64] = h; Al[akq + 0][arow + 64] = l;
        split_tf32(a2.y, h, l); Ah[akq + 1][arow + 64] = h; Al[akq + 1][arow + 64] = l;
        split_tf32(a2.z, h, l); Ah[akq + 2][arow + 64] = h; Al[akq + 2][arow + 64] = l;
        split_tf32(a2.w, h, l); Ah[akq + 3][arow + 64] = h; Al[akq + 3][arow + 64] = l;
        split_tf32(b.x, h, l);  Bh[akq + 0][arow] = h; Bl[akq + 0][arow] = l;
        split_tf32(b.y, h, l);  Bh[akq + 1][arow] = h; Bl[akq + 1][arow] = l;
        split_tf32(b.z, h, l);  Bh[akq + 2][arow] = h; Bl[akq + 2][arow] = l;
        split_tf32(b.w, h, l);  Bh[akq + 3][arow] = h; Bl[akq + 3][arow] = l;
    };
    store_tiles(ra1, ra2, rb);
    __syncthreads();

    for (int t = 0; t < nk; t++) {
        if (t + 1 < nk) {
            ra1 = *(const float4*)(Ap1 + (t + 1) * 16);
            ra2 = *(const float4*)(Ap2 + (t + 1) * 16);
            rb  = *(const float4*)(Bp  + (t + 1) * 16);
        }
#pragma unroll
        for (int kk = 0; kk < 16; kk += 8) {
            unsigned afh[2][4], afl[2][4], bfh[4][2], bfl[4][2];
#pragma unroll
            for (int mt = 0; mt < 2; mt++) {
                int mb = mw + mt * 16 + g;
                afh[mt][0] = Ah[kk + tig][mb];     afl[mt][0] = Al[kk + tig][mb];
                afh[mt][1] = Ah[kk + tig][mb + 8]; afl[mt][1] = Al[kk + tig][mb + 8];
                afh[mt][2] = Ah[kk + tig + 4][mb];     afl[mt][2] = Al[kk + tig + 4][mb];
                afh[mt][3] = Ah[kk + tig + 4][mb + 8]; afl[mt][3] = Al[kk + tig + 4][mb + 8];
            }
#pragma unroll
            for (int nt = 0; nt < 4; nt++) {
                int nb = nw + nt * 8 + g;
                bfh[nt][0] = Bh[kk + tig][nb];     bfl[nt][0] = Bl[kk + tig][nb];
                bfh[nt][1] = Bh[kk + tig + 4][nb]; bfl[nt][1] = Bl[kk + tig + 4][nb];
            }
#pragma unroll
            for (int mt = 0; mt < 2; mt++)
#pragma unroll
                for (int nt = 0; nt < 4; nt++) {
                    mma_tf32(acc[mt][nt], afl[mt], bfh[nt]);
                    mma_tf32(acc[mt][nt], afh[mt], bfl[nt]);
                    mma_tf32(acc[mt][nt], afh[mt], bfh[nt]);
                }
        }
        __syncthreads();
        if (t + 1 < nk) {
            store_tiles(ra1, ra2, rb);
            __syncthreads();
        }
    }

#pragma unroll
    for (int mt = 0; mt < 2; mt++)
#pragma unroll
        for (int nt = 0; nt < 4; nt++) {
            int row = m0 + mw + mt * 16 + g;
            int col = n0 + nw + nt * 8 + 2 * tig;
            float b0 = bias ? bias[col] : 0.0f;
            float b1 = bias ? bias[col + 1] : 0.0f;
            C[(long long)row * ldc + col]           = acc[mt][nt][0] * scale + b0;
            C[(long long)row * ldc + col + 1]       = acc[mt][nt][1] * scale + b1;
            C[(long long)(row + 8) * ldc + col]     = acc[mt][nt][2] * scale + b0;
            C[(long long)(row + 8) * ldc + col + 1] = acc[mt][nt][3] * scale + b1;
        }
}

// ---------------- softmax row stats: max + 1/sum(exp) per (head,row) ----------------
__global__ void stats_kernel(long long sOff, long long statsOff, int Ts) {
    int h = blockIdx.y, t = blockIdx.x;
    const float* row = g_scratch + sOff + ((long long)h * Ts + t) * Ts;
    float* stats = g_scratch + statsOff;
    __shared__ float red[256];
    int tid = threadIdx.x;
    float m = -1e30f;
    for (int s = tid; s < Ts; s += 256) m = fmaxf(m, row[s]);
    red[tid] = m; __syncthreads();
    for (int st = 128; st > 0; st >>= 1) {
        if (tid < st) red[tid] = fmaxf(red[tid], red[tid + st]);
        __syncthreads();
    }
    m = red[0]; __syncthreads();
    float sum = 0.0f;
    for (int s = tid; s < Ts; s += 256) sum += __expf(row[s] - m);
    red[tid] = sum; __syncthreads();
    for (int st = 128; st > 0; st >>= 1) {
        if (tid < st) red[tid] += red[tid + st];
        __syncthreads();
    }
    if (tid == 0) {
        stats[((long long)h * Ts + t) * 2] = m;
        stats[((long long)h * Ts + t) * 2 + 1] = 1.0f / red[0];
    }
}

// ---------------- AV via 3xTF32 tensor cores: O = softmax(S) @ V ----------------
// CTA: 64 t-rows x HDv cols, s-tiles of SB. P computed (exp) on the fly, split hi/lo.
template <int HDv, int SB>
__global__ void __launch_bounds__(256) av_tf32(
    long long sOff, long long statsOff,
    const float* __restrict__ Vext, long long vOff, int vrs,
    long long oOff, int ors, int Ts) {
    int h = blockIdx.y;
    int t0 = blockIdx.x * 64;
    const float* V = Vext ? Vext : g_scratch + vOff;
    float* O = g_scratch + oOff;
    const float* Sp = g_scratch + sOff + ((long long)h * Ts + t0) * Ts;
    const float* st = g_scratch + statsOff + ((long long)h * Ts + t0) * 2;

    __shared__ unsigned Ah[SB][68], Al[SB][68];            // [s][t] P tile (transposed)
    __shared__ unsigned Bh[SB][HDv + 4], Bl[SB][HDv + 4];  // [s][d] V tile
    __shared__ float smx[64], srd[64];

    int tid = threadIdx.x, lane = tid & 31, wp = tid >> 5;
    int g = lane >> 2, tig = lane & 3;
    if (tid < 64) { smx[tid] = st[tid * 2]; srd[tid] = st[tid * 2 + 1]; }
    __syncthreads();

    constexpr int NW = HDv / 32;       // warps along n
    constexpr int MW = 8 / NW;         // warps along m
    constexpr int MT = (64 / MW) / 16; // m16 tiles per warp
    int wr = wp / NW, wc = wp % NW;
    int mw = wr * (64 / MW), nw = wc * 32;

    float acc[MT][4][4];
#pragma unroll
    for (int a = 0; a < MT; a++)
#pragma unroll
        for (int b = 0; b < 4; b++)
#pragma unroll
            for (int c = 0; c < 4; c++) acc[a][b][c] = 0.0f;

    int prow = tid >> 2, pq = (tid & 3) << 2;
    float pm = smx[prow], pr = srd[prow];

    for (int s0 = 0; s0 < Ts; s0 += SB) {
        // P tile: 64 x SB, exp applied, stored transposed A[s][t], hi/lo split
        {
            const float* sp = Sp + (long long)prow * Ts + s0;
            unsigned hh, ll;
            float4 s1 = *(const float4*)(sp + pq);
            split_tf32(__expf(s1.x - pm) * pr, hh, ll); Ah[pq + 0][prow] = hh; Al[pq + 0][prow] = ll;
            split_tf32(__expf(s1.y - pm) * pr, hh, ll); Ah[pq + 1][prow] = hh; Al[pq + 1][prow] = ll;
            split_tf32(__expf(s1.z - pm) * pr, hh, ll); Ah[pq + 2][prow] = hh; Al[pq + 2][prow] = ll;
            split_tf32(__expf(s1.w - pm) * pr, hh, ll); Ah[pq + 3][prow] = hh; Al[pq + 3][prow] = ll;
            if (SB == 32) {
                float4 s2 = *(const float4*)(sp + pq + 16);
                split_tf32(__expf(s2.x - pm) * pr, hh, ll); Ah[pq + 16][prow] = hh; Al[pq + 16][prow] = ll;
                split_tf32(__expf(s2.y - pm) * pr, hh, ll); Ah[pq + 17][prow] = hh; Al[pq + 17][prow] = ll;
                split_tf32(__expf(s2.z - pm) * pr, hh, ll); Ah[pq + 18][prow] = hh; Al[pq + 18][prow] = ll;
                split_tf32(__expf(s2.w - pm) * pr, hh, ll); Ah[pq + 19][prow] = hh; Al[pq + 19][prow] = ll;
            }
        }
        // V tile: SB x HDv, hi/lo split
        {
            unsigned hh, ll;
            if (HDv == 64) {  // SB == 32: 32x64, 2 rows-of-16 per thread pass
                int vrow = tid >> 4, vq = (tid & 15) << 2;
#pragma unroll
                for (int rr = 0; rr < 2; rr++) {
                    int r = vrow + rr * 16;
                    float4 v = *(const float4*)(V + (long long)(s0 + r) * vrs + h * HDv + vq);
                    split_tf32(v.x, hh, ll); Bh[r][vq + 0] = hh; Bl[r][vq + 0] = ll;
                    split_tf32(v.y, hh, ll); Bh[r][vq + 1] = hh; Bl[r][vq + 1] = ll;
                    split_tf32(v.z, hh, ll); Bh[r][vq + 2] = hh; Bl[r][vq + 2] = ll;
                    split_tf32(v.w, hh, ll); Bh[r][vq + 3] = hh; Bl[r][vq + 3] = ll;
                }
            } else {          // HDv == 128, SB == 16: 16x128
                int vrow = tid >> 5, vq = (tid & 31) << 2;
#pragma unroll
                for (int rr = 0; rr < 2; rr++) {
                    int r = vrow + rr * 8;
                    float4 v = *(const float4*)(V + (long long)(s0 + r) * vrs + h * HDv + vq);
                    split_tf32(v.x, hh, ll); Bh[r][vq + 0] = hh; Bl[r][vq + 0] = ll;
                    split_tf32(v.y, hh, ll); Bh[r][vq + 1] = hh; Bl[r][vq + 1] = ll;
                    split_tf32(v.z, hh, ll); Bh[r][vq + 2] = hh; Bl[r][vq + 2] = ll;
                    split_tf32(v.w, hh, ll); Bh[r][vq + 3] = hh; Bl[r][vq + 3] = ll;
                }
            }
        }
        __syncthreads();
#pragma unroll
        for (int kk = 0; kk < SB; kk += 8) {
            unsigned afh[MT][4], afl[MT][4], bfh[4][2], bfl[4][2];
#pragma unroll
            for (int mt = 0; mt < MT; mt++) {
                int mb = mw + mt * 16 + g;
                afh[mt][0] = Ah[kk + tig][mb];     afl[mt][0] = Al[kk + tig][mb];
                afh[mt][1] = Ah[kk + tig][mb + 8]; afl[mt][1] = Al[kk + tig][mb + 8];
                afh[mt][2] = Ah[kk + tig + 4][mb];     afl[mt][2] = Al[kk + tig + 4][mb];
                afh[mt][3] = Ah[kk + tig + 4][mb + 8]; afl[mt][3] = Al[kk + tig + 4][mb + 8];
            }
#pragma unroll
            for (int nt = 0; nt < 4; nt++) {
                int nb = nw + nt * 8 + g;
                bfh[nt][0] = Bh[kk + tig][nb];     bfl[nt][0] = Bl[kk + tig][nb];
                bfh[nt][1] = Bh[kk + tig + 4][nb]; bfl[nt][1] = Bl[kk + tig + 4][nb];
            }
#pragma unroll
            for (int mt = 0; mt < MT; mt++)
#pragma unroll
                for (int nt = 0; nt < 4; nt++) {
                    mma_tf32(acc[mt][nt], afl[mt], bfh[nt]);
                    mma_tf32(acc[mt][nt], afh[mt], bfl[nt]);
                    mma_tf32(acc[mt][nt], afh[mt], bfh[nt]);
                }
        }
        __syncthreads();
    }

#pragma unroll
    for (int mt = 0; mt < MT; mt++)
#pragma unroll
        for (int nt = 0; nt < 4; nt++) {
            int row = t0 + mw + mt * 16 + g;
            int col = h * HDv + nw + nt * 8 + 2 * tig;
            O[(long long)row * ors + col]           = acc[mt][nt][0];
            O[(long long)row * ors + col + 1]       = acc[mt][nt][1];
            O[(long long)(row + 8) * ors + col]     = acc[mt][nt][2];
            O[(long long)(row + 8) * ors + col + 1] = acc[mt][nt][3];
        }
}

// ---------------- combined slice j: out_j += c/16 * sum_{h<4} softmax(S)[h,t,s] ----------------
// c = sp[0] + sp[1] + sp[3]  (broadcast quirk: every slice gets the same scalar)
__global__ void __launch_bounds__(256) combined_add(
    long long sOff, long long statsOff,
    const float* __restrict__ sp, float* __restrict__ out, int accumulate) {
    int t0 = blockIdx.y * 64, s0 = blockIdx.x * 64;
    const float* stats = g_scratch + statsOff;
    __shared__ float smx[4][64], srd[4][64];
    int tid = threadIdx.x;
    {
        int hh = tid >> 6, t = tid & 63;
        smx[hh][t] = stats[((long long)hh * TT + t0 + t) * 2];
        srd[hh][t] = stats[((long long)hh * TT + t0 + t) * 2 + 1];
    }
    __syncthreads();
    int ty = tid >> 4, tx = tid & 15;
    float acc[4][4] = {};
    for (int h = 0; h < 4; h++) {
        const float* Sp = g_scratch + sOff + ((long long)h * TT + t0) * TT + s0;
#pragma unroll
        for (int i = 0; i < 4; i++) {
            int t = ty * 4 + i;
            float m = smx[h][t], r = srd[h][t];
            float4 sv = *(const float4*)(Sp + (long long)t * TT + tx * 4);
            acc[i][0] += __expf(sv.x - m) * r;
            acc[i][1] += __expf(sv.y - m) * r;
            acc[i][2] += __expf(sv.z - m) * r;
            acc[i][3] += __expf(sv.w - m) * r;
        }
    }
    float coeff = (sp[0] + sp[1] + sp[3]) * (1.0f / 16.0f);
#pragma unroll
    for (int i = 0; i < 4; i++)
#pragma unroll
        for (int j = 0; j < 4; j++) {
            long long o = (long long)(t0 + ty * 4 + i) * TT + s0 + tx * 4 + j;
            float v = coeff * acc[i][j];
            if (accumulate) v += out[o];
            out[o] = v;
        }
}

// ---------------- linear interpolation of g_small [256,1024] -> hier_in[:,1024:2048] ----------------
__global__ void interp_kernel(long long gsOff, long long hinOff) {
    const float* gsmall = g_scratch + gsOff;
    float* hin = g_scratch + hinOff;
    int idx = blockIdx.x * 256 + threadIdx.x;
    if (idx >= TT * DD) return;
    int t = idx >> 10, c = idx & 1023;
    float src = (t + 0.5f) * (256.0f / 2048.0f) - 0.5f;
    src = fminf(fmaxf(src, 0.0f), 255.0f);
    int i0 = (int)floorf(src);
    int i1 = min(i0 + 1, 255);
    float w = src - (float)i0;
    hin[(long long)t * 2048 + 1024 + c] = gsmall[i0 * 1024 + c] * (1.0f - w) + gsmall[i1 * 1024 + c] * w;
}

// ---------------- weighted = p0*lin + p1*sparse + p2*hier + p3*quantum ----------------
__global__ void weighted_kernel(const float* __restrict__ sp,
                                long long aOff, long long bOff, long long cOff, long long dOff,
                                float* __restrict__ out) {
    int idx = blockIdx.x * 256 + threadIdx.x;
    if (idx >= TT * DD) return;
    out[idx] = sp[0] * g_scratch[aOff + idx] + sp[1] * g_scratch[bOff + idx]
             + sp[2] * g_scratch[cOff + idx] + sp[3] * g_scratch[dOff + idx];
}

// ---------------- host launcher: kernel launches ONLY ----------------
extern "C" void kernel_launch(void* const* d_in, const int* in_sizes, int n_in,
                              void* d_out, int out_size) {
    const float* query = (const float*)d_in[0];
    const float* key   = (const float*)d_in[1];
    const float* value = (const float*)d_in[2];
    const float* sp    = (const float*)d_in[3];
    const float* Wqkv_lin = (const float*)d_in[4];
    const float* b_lin  = (const float*)d_in[5];
    const float* Wo_lin = (const float*)d_in[6];
    const float* bo_lin = (const float*)d_in[7];
    const float* spars  = (const float*)d_in[8];
    const float* Wqkv_loc = (const float*)d_in[9];
    const float* b_loc  = (const float*)d_in[10];
    const float* Wo_loc = (const float*)d_in[11];
    const float* bo_loc = (const float*)d_in[12];
    const float* Wqkv_glb = (const float*)d_in[13];
    const float* b_glb  = (const float*)d_in[14];
    const float* Wo_glb = (const float*)d_in[15];
    const float* bo_glb = (const float*)d_in[16];
    const float* Wf = (const float*)d_in[17];
    const float* bf = (const float*)d_in[18];
    const float* Rq = (const float*)d_in[19];
    const float* ent = (const float*)d_in[20];

    float* out = (float*)d_out;
    float* comb0 = out + (size_t)TT * DD;       // linear_w
    float* comb1 = comb0 + (size_t)TT * TT;     // sparse_w
    float* comb2 = comb1 + (size_t)TT * TT;     // quantum_w

    const long long TT2 = (long long)TT * TT;

    prep_kernel<<<256, 256>>>(Rq, spars, ent);

    dim3 gProj(16, 16, 1);       // N/64=16, M/128=16
    dim3 gScores4(32, 16, 4);    // N/64=32, M/128=16, 4 heads
    dim3 gComb(32, 32);

    // ===== Linear MHA (4 head-groups of 4) =====
    gemm_tf32<<<gProj, 256>>>(query, 0, 0, DD, Wqkv_lin, 0, 0, DD, b_lin, -1, OFF_Q, 0, DD, TT, DD, DD);
    gemm_tf32<<<gProj, 256>>>(key,   0, 0, DD, Wqkv_lin + DD * DD, 0, 0, DD, b_lin + DD, -1, OFF_K, 0, DD, TT, DD, DD);
    gemm_tf32<<<gProj, 256>>>(value, 0, 0, DD, Wqkv_lin + 2 * DD * DD, 0, 0, DD, b_lin + 2 * DD, -1, OFF_V, 0, DD, TT, DD, DD);
    for (int g = 0; g < 4; g++) {
        long long ho = (long long)g * 256;   // 4 heads * 64 dims
        gemm_tf32<<<gScores4, 256>>>(nullptr, OFF_Q + ho, 64, DD, nullptr, OFF_K + ho, 64, DD, nullptr, OFF_SCALES + g * 4, OFF_S, TT2, TT, TT, TT, 64);
        stats_kernel<<<dim3(TT, 4), 256>>>(OFF_S, OFF_STATS, TT);
        av_tf32<64, 32><<<dim3(32, 4), 256>>>(OFF_S, OFF_STATS, nullptr, OFF_V + ho, DD, OFF_AO + ho, DD, TT);
        combined_add<<<gComb, 256>>>(OFF_S, OFF_STATS, sp, comb0, g == 0 ? 0 : 1);
    }
    gemm_tf32<<<gProj, 256>>>(nullptr, OFF_AO, 0, DD, Wo_lin, 0, 0, DD, bo_lin, -1, OFF_LIN, 0, DD, TT, DD, DD);

    // ===== Sparse (raw heads, masked scale) =====
    for (int g = 0; g < 4; g++) {
        long long ho = (long long)g * 256;
        gemm_tf32<<<gScores4, 256>>>(query + ho, 0, 64, DD, key + ho, 0, 64, DD, nullptr, OFF_SCALES + 16 + g * 4, OFF_S, TT2, TT, TT, TT, 64);
        stats_kernel<<<dim3(TT, 4), 256>>>(OFF_S, OFF_STATS, TT);
        av_tf32<64, 32><<<dim3(32, 4), 256>>>(OFF_S, OFF_STATS, value + ho, 0, DD, OFF_SP + ho, DD, TT);
        combined_add<<<gComb, 256>>>(OFF_S, OFF_STATS, sp, comb1, g == 0 ? 0 : 1);
    }

    // ===== Quantum (rotated heads, gated scale) =====
    gemm_tf32<<<dim3(1, 16, 16), 256>>>(query, 0, 64, DD, nullptr, OFF_RT, 4096, 64, nullptr, -1, OFF_Q, 64, DD, TT, 64, 64);
    gemm_tf32<<<dim3(1, 16, 16), 256>>>(key,   0, 64, DD, nullptr, OFF_RT, 4096, 64, nullptr, -1, OFF_K, 64, DD, TT, 64, 64);
    for (int g = 0; g < 4; g++) {
        long long ho = (long long)g * 256;
        gemm_tf32<<<gScores4, 256>>>(nullptr, OFF_Q + ho, 64, DD, nullptr, OFF_K + ho, 64, DD, nullptr, OFF_SCALES + 32 + g * 4, OFF_S, TT2, TT, TT, TT, 64);
        stats_kernel<<<dim3(TT, 4), 256>>>(OFF_S, OFF_STATS, TT);
        av_tf32<64, 32><<<dim3(32, 4), 256>>>(OFF_S, OFF_STATS, value + ho, 0, DD, OFF_QT + ho, DD, TT);
        combined_add<<<gComb, 256>>>(OFF_S, OFF_STATS, sp, comb2, g == 0 ? 0 : 1);
    }

    // ===== Local MHA (8 heads of 128, 2 groups of 4) =====
    gemm_tf32<<<gProj, 256>>>(query, 0, 0, DD, Wqkv_loc, 0, 0, DD, b_loc, -1, OFF_Q, 0, DD, TT, DD, DD);
    gemm_tf32<<<gProj, 256>>>(key,   0, 0, DD, Wqkv_loc + DD * DD, 0, 0, DD, b_loc + DD, -1, OFF_K, 0, DD, TT, DD, DD);
    gemm_tf32<<<gProj, 256>>>(value, 0, 0, DD, Wqkv_loc + 2 * DD * DD, 0, 0, DD, b_loc + 2 * DD, -1, OFF_V, 0, DD, TT, DD, DD);
    for (int g = 0; g < 2; g++) {
        long long ho = (long long)g * 512;   // 4 heads * 128 dims
        gemm_tf32<<<gScores4, 256>>>(nullptr, OFF_Q + ho, 128, DD, nullptr, OFF_K + ho, 128, DD, nullptr, OFF_SCALES + 48 + g * 4, OFF_S, TT2, TT, TT, TT, 128);
        stats_kernel<<<dim3(TT, 4), 256>>>(OFF_S, OFF_STATS, TT);
        av_tf32<128, 16><<<dim3(32, 4), 256>>>(OFF_S, OFF_STATS, nullptr, OFF_V + ho, DD, OFF_AO + ho, DD, TT);
    }
    gemm_tf32<<<gProj, 256>>>(nullptr, OFF_AO, 0, DD, Wo_loc, 0, 0, DD, bo_loc, -1, OFF_HIN, 0, 2048, TT, DD, DD);

    // ===== Global MHA (subsampled tokens stride 8, 8 heads of 128) =====
    dim3 gProjG(16, 2, 1);  // M=256 -> 2 blocks of 128
    gemm_tf32<<<gProjG, 256>>>(query, 0, 0, 8 * DD, Wqkv_glb, 0, 0, DD, b_glb, -1, OFF_GQ, 0, DD, TG, DD, DD);
    gemm_tf32<<<gProjG, 256>>>(key,   0, 0, 8 * DD, Wqkv_glb + DD * DD, 0, 0, DD, b_glb + DD, -1, OFF_GK, 0, DD, TG, DD, DD);
    gemm_tf32<<<gProjG, 256>>>(value, 0, 0, 8 * DD, Wqkv_glb + 2 * DD * DD, 0, 0, DD, b_glb + 2 * DD, -1, OFF_GV, 0, DD, TG, DD, DD);
    gemm_tf32<<<dim3(4, 2, 8), 256>>>(nullptr, OFF_GQ, 128, DD, nullptr, OFF_GK, 128, DD, nullptr, OFF_SCALES + 48, OFF_S, (long long)TG * TG, TG, TG, TG, 128);
    stats_kernel<<<dim3(TG, 8), 256>>>(OFF_S, OFF_STATS, TG);
    av_tf32<128, 16><<<dim3(4, 8), 256>>>(OFF_S, OFF_STATS, nullptr, OFF_GV, DD, OFF_GAO, DD, TG);
    gemm_tf32<<<gProjG, 256>>>(nullptr, OFF_GAO, 0, DD, Wo_glb, 0, 0, DD, bo_glb, -1, OFF_GSM, 0, DD, TG, DD, DD);
    interp_kernel<<<(TT * DD + 255) / 256, 256>>>(OFF_GSM, OFF_HIN);

    // ===== Hierarchical fuse: [local|global] @ Wf^T + bf =====
    gemm_tf32<<<gProj, 256>>>(nullptr, OFF_HIN, 0, 2048, Wf, 0, 0, 2048, bf, -1, OFF_HOUT, 0, DD, TT, DD, 2048);

    // ===== Weighted combination =====
    weighted_kernel<<<(TT * DD + 255) / 256, 256>>>(sp, OFF_LIN, OFF_SP, OFF_HOUT, OFF_QT, out);
}

// round 13
// speedup vs baseline: 1.9271x; 1.2329x over previous
#include <cuda_runtime.h>
#include <math.h>

// ---------------- problem constants ----------------
#define TT 2048
#define DD 1024
#define TG 256      // global tokens (stride 8)

// ---------------- one scratch block; head-grouped S keeps total < 160 MB ----------------
constexpr long long SZ_S     = 4LL * 2048 * 2048;   // 4 heads per group
constexpr long long SZ_STATS = 16LL * 2048 * 2;
constexpr long long SZ_MAT   = 2048LL * 1024;
constexpr long long SZ_HIN   = 2048LL * 2048;
constexpr long long SZ_G     = 256LL * 1024;
constexpr long long SZ_RT    = 16LL * 64 * 64;

constexpr long long OFF_S      = 0;
constexpr long long OFF_STATS  = OFF_S + SZ_S;
constexpr long long OFF_Q      = OFF_STATS + SZ_STATS;
constexpr long long OFF_K      = OFF_Q + SZ_MAT;
constexpr long long OFF_V      = OFF_K + SZ_MAT;
constexpr long long OFF_AO     = OFF_V + SZ_MAT;
constexpr long long OFF_LIN    = OFF_AO + SZ_MAT;
constexpr long long OFF_SP     = OFF_LIN + SZ_MAT;
constexpr long long OFF_QT     = OFF_SP + SZ_MAT;
constexpr long long OFF_HIN    = OFF_QT + SZ_MAT;
constexpr long long OFF_HOUT   = OFF_HIN + SZ_HIN;
constexpr long long OFF_GQ     = OFF_HOUT + SZ_MAT;
constexpr long long OFF_GK     = OFF_GQ + SZ_G;
constexpr long long OFF_GV     = OFF_GK + SZ_G;
constexpr long long OFF_GAO    = OFF_GV + SZ_G;
constexpr long long OFF_GSM    = OFF_GAO + SZ_G;
constexpr long long OFF_RT     = OFF_GSM + SZ_G;
constexpr long long OFF_SCALES = OFF_RT + SZ_RT;
constexpr long long SCRATCH_TOTAL = OFF_SCALES + 64;   // ~39.2M floats = 157 MB

__device__ float g_scratch[SCRATCH_TOTAL];

// ---------------- tf32 helpers ----------------
__device__ __forceinline__ unsigned f2tf(float f) {
    unsigned u;
    asm("cvt.rna.tf32.f32 %0, %1;" : "=r"(u) : "f"(f));
    return u;
}
// 3xTF32 split: x ~= hi + lo, each representable in tf32
__device__ __forceinline__ void split_tf32(float x, unsigned& hi, unsigned& lo) {
    hi = f2tf(x);
    lo = f2tf(x - __uint_as_float(hi));
}
__device__ __forceinline__ void mma_tf32(float* d, const unsigned* a, const unsigned* b) {
    asm volatile(
        "mma.sync.aligned.m16n8k8.row.col.f32.tf32.tf32.f32 "
        "{%0,%1,%2,%3}, {%4,%5,%6,%7}, {%8,%9}, {%0,%1,%2,%3};"
        : "+f"(d[0]), "+f"(d[1]), "+f"(d[2]), "+f"(d[3])
        : "r"(a[0]), "r"(a[1]), "r"(a[2]), "r"(a[3]), "r"(b[0]), "r"(b[1]));
}
__device__ __forceinline__ void cp_async16(void* smem_dst, const void* gsrc) {
    unsigned dst = (unsigned)__cvta_generic_to_shared(smem_dst);
    asm volatile("cp.async.ca.shared.global [%0], [%1], 16;\n" :: "r"(dst), "l"(gsrc));
}
#define CP_COMMIT() asm volatile("cp.async.commit_group;\n" ::: "memory")
#define CP_WAIT0()  asm volatile("cp.async.wait_group 0;\n" ::: "memory")

// ---------------- prep: transpose R_quant, build per-head score scales ----------------
__global__ void prep_kernel(const float* __restrict__ R, const float* __restrict__ spars,
                            const float* __restrict__ ent) {
    float* Rt = g_scratch + OFF_RT;
    float* scales = g_scratch + OFF_SCALES;
    int idx = blockIdx.x * 256 + threadIdx.x;
    if (idx < 16 * 64 * 64) {
        int h = idx >> 12, rem = idx & 4095;
        int d = rem >> 6, e = rem & 63;
        Rt[h * 4096 + e * 64 + d] = R[h * 4096 + d * 64 + e];
    }
    if (idx < 16) {
        scales[idx] = 0.125f;                                   // 1/sqrt(64)
        scales[16 + idx] = (spars[idx] > 0.0f) ? 0.125f : 0.0f; // sigmoid(x)>0.5 <=> x>0
        float g = 1.0f / (1.0f + __expf(-ent[idx * 4]));        // ent_gate[h,0,0]
        scales[32 + idx] = g * 0.125f;
    }
    if (idx < 8) scales[48 + idx] = 0.08838834764831845f;       // 1/sqrt(128)
}

// ---------------- 3xTF32 tensor-core GEMM: C[z] = scale[z] * A[z] @ B[z]^T + bias ----------------
// CTA tile 128x64, BK=16, 8 warps of 32x32. Raw fp32 in smem (cp.async, double-buffered);
// hi/lo split happens at fragment-load time.
// Requires: M % 128 == 0, N % 64 == 0, K % 16 == 0 (all call sites satisfy this).
#define ASTRIDE 20   // row stride in floats; (20*m + k) % 32 distinct across the frag-load warp
__global__ void __launch_bounds__(256) gemm_tf32(
    const float* __restrict__ Aext, long long aOff, long long aStride, int lda,
    const float* __restrict__ Bext, long long bOff, long long bStride, int ldb,
    const float* __restrict__ bias,
    long long scaleOff,
    long long cOff, long long cStride, int ldc,
    int M, int N, int K) {
    int z = blockIdx.z;
    const float* A = (Aext ? Aext : g_scratch + aOff) + z * aStride;
    const float* B = (Bext ? Bext : g_scratch + bOff) + z * bStride;
    float* C = g_scratch + cOff + z * cStride;
    float scale = (scaleOff >= 0) ? g_scratch[scaleOff + z] : 1.0f;
    int m0 = blockIdx.y * 128, n0 = blockIdx.x * 64;

    __shared__ float As[2][128][ASTRIDE];   // [m][k]
    __shared__ float Bs[2][64][ASTRIDE];    // [n][k]

    int tid = threadIdx.x, lane = tid & 31, wp = tid >> 5;
    int g = lane >> 2, tig = lane & 3;
    int wr = wp >> 1, wc = wp & 1;
    int mw = wr * 32, nw = wc * 32;

    float acc[2][4][4];
#pragma unroll
    for (int a = 0; a < 2; a++)
#pragma unroll
        for (int b = 0; b < 4; b++)
#pragma unroll
            for (int c = 0; c < 4; c++) acc[a][b][c] = 0.0f;

    // cp.async tile loaders: A = 128 rows x 16 floats (512 x 16B chunks, 2/thread),
    //                        B = 64 rows (256 chunks, 1/thread)
    int ar0 = tid >> 2, akq = (tid & 3) << 2;       // chunk 0: rows 0..63
    int ar1 = (tid + 256) >> 2;                      // chunk 1: rows 64..127
    auto load_tile = [&](int buf, int t) {
        int k0 = t * 16;
        cp_async16(&As[buf][ar0][akq], A + (long long)(m0 + ar0) * lda + k0 + akq);
        cp_async16(&As[buf][ar1][akq], A + (long long)(m0 + ar1) * lda + k0 + akq);
        cp_async16(&Bs[buf][ar0][akq], B + (long long)(n0 + ar0) * ldb + k0 + akq);
    };

    int nk = K >> 4;
    load_tile(0, 0);
    CP_COMMIT();
    CP_WAIT0();
    __syncthreads();

    for (int t = 0; t < nk; t++) {
        if (t + 1 < nk) {
            load_tile((t + 1) & 1, t + 1);
            CP_COMMIT();
        }
        int buf = t & 1;
#pragma unroll
        for (int kk = 0; kk < 16; kk += 8) {
            unsigned afh[2][4], afl[2][4], bfh[4][2], bfl[4][2];
#pragma unroll
            for (int mt = 0; mt < 2; mt++) {
                int mb = mw + mt * 16 + g;
                split_tf32(As[buf][mb][kk + tig],         afh[mt][0], afl[mt][0]);
                split_tf32(As[buf][mb + 8][kk + tig],     afh[mt][1], afl[mt][1]);
                split_tf32(As[buf][mb][kk + tig + 4],     afh[mt][2], afl[mt][2]);
                split_tf32(As[buf][mb + 8][kk + tig + 4], afh[mt][3], afl[mt][3]);
            }
#pragma unroll
            for (int nt = 0; nt < 4; nt++) {
                int nb = nw + nt * 8 + g;
                split_tf32(Bs[buf][nb][kk + tig],     bfh[nt][0], bfl[nt][0]);
                split_tf32(Bs[buf][nb][kk + tig + 4], bfh[nt][1], bfl[nt][1]);
            }
#pragma unroll
            for (int mt = 0; mt < 2; mt++)
#pragma unroll
                for (int nt = 0; nt < 4; nt++) {
                    mma_tf32(acc[mt][nt], afl[mt], bfh[nt]);
                    mma_tf32(acc[mt][nt], afh[mt], bfl[nt]);
                    mma_tf32(acc[mt][nt], afh[mt], bfh[nt]);
                }
        }
        if (t + 1 < nk) {
            CP_WAIT0();
            __syncthreads();
        }
    }

#pragma unroll
    for (int mt = 0; mt < 2; mt++)
#pragma unroll
        for (int nt = 0; nt < 4; nt++) {
            int row = m0 + mw + mt * 16 + g;
            int col = n0 + nw + nt * 8 + 2 * tig;
            float b0 = bias ? bias[col] : 0.0f;
            float b1 = bias ? bias[col + 1] : 0.0f;
            C[(long long)row * ldc + col]           = acc[mt][nt][0] * scale + b0;
            C[(long long)row * ldc + col + 1]       = acc[mt][nt][1] * scale + b1;
            C[(long long)(row + 8) * ldc + col]     = acc[mt][nt][2] * scale + b0;
            C[(long long)(row + 8) * ldc + col + 1] = acc[mt][nt][3] * scale + b1;
        }
}

// ---------------- softmax row stats: max + 1/sum(exp) per (head,row) ----------------
__global__ void stats_kernel(long long sOff, long long statsOff, int Ts) {
    int h = blockIdx.y, t = blockIdx.x;
    const float* row = g_scratch + sOff + ((long long)h * Ts + t) * Ts;
    float* stats = g_scratch + statsOff;
    __shared__ float red[256];
    int tid = threadIdx.x;
    float m = -1e30f;
    for (int s = tid; s < Ts; s += 256) m = fmaxf(m, row[s]);
    red[tid] = m; __syncthreads();
    for (int st = 128; st > 0; st >>= 1) {
        if (tid < st) red[tid] = fmaxf(red[tid], red[tid + st]);
        __syncthreads();
    }
    m = red[0]; __syncthreads();
    float sum = 0.0f;
    for (int s = tid; s < Ts; s += 256) sum += __expf(row[s] - m);
    red[tid] = sum; __syncthreads();
    for (int st = 128; st > 0; st >>= 1) {
        if (tid < st) red[tid] += red[tid + st];
        __syncthreads();
    }
    if (tid == 0) {
        stats[((long long)h * Ts + t) * 2] = m;
        stats[((long long)h * Ts + t) * 2 + 1] = 1.0f / red[0];
    }
}

// ---------------- AV via 3xTF32 tensor cores: O = softmax(S) @ V ----------------
// CTA: 64 t-rows x HDv cols, s-tiles of SB. Raw fp32 in smem; split at frag load.
template <int HDv, int SB>
__global__ void __launch_bounds__(256) av_tf32(
    long long sOff, long long statsOff,
    const float* __restrict__ Vext, long long vOff, int vrs,
    long long oOff, int ors, int Ts) {
    int h = blockIdx.y;
    int t0 = blockIdx.x * 64;
    const float* V = Vext ? Vext : g_scratch + vOff;
    float* O = g_scratch + oOff;
    const float* Sp = g_scratch + sOff + ((long long)h * Ts + t0) * Ts;
    const float* st = g_scratch + statsOff + ((long long)h * Ts + t0) * 2;

    __shared__ float As[SB][68];            // [s][t] P tile (transposed)
    __shared__ float Bs[SB][HDv + 4];       // [s][d] V tile
    __shared__ float smx[64], srd[64];

    int tid = threadIdx.x, lane = tid & 31, wp = tid >> 5;
    int g = lane >> 2, tig = lane & 3;
    if (tid < 64) { smx[tid] = st[tid * 2]; srd[tid] = st[tid * 2 + 1]; }
    __syncthreads();

    constexpr int NW = HDv / 32;       // warps along n
    constexpr int MW = 8 / NW;         // warps along m
    constexpr int MT = (64 / MW) / 16; // m16 tiles per warp
    int wr = wp / NW, wc = wp % NW;
    int mw = wr * (64 / MW), nw = wc * 32;

    float acc[MT][4][4];
#pragma unroll
    for (int a = 0; a < MT; a++)
#pragma unroll
        for (int b = 0; b < 4; b++)
#pragma unroll
            for (int c = 0; c < 4; c++) acc[a][b][c] = 0.0f;

    int prow = tid >> 2, pq = (tid & 3) << 2;
    float pm = smx[prow], pr = srd[prow];

    for (int s0 = 0; s0 < Ts; s0 += SB) {
        // P tile: 64 x SB, exp applied, stored transposed As[s][t]
        {
            const float* sp = Sp + (long long)prow * Ts + s0;
            float4 s1 = *(const float4*)(sp + pq);
            As[pq + 0][prow] = __expf(s1.x - pm) * pr;
            As[pq + 1][prow] = __expf(s1.y - pm) * pr;
            As[pq + 2][prow] = __expf(s1.z - pm) * pr;
            As[pq + 3][prow] = __expf(s1.w - pm) * pr;
            if (SB == 32) {
                float4 s2 = *(const float4*)(sp + pq + 16);
                As[pq + 16][prow] = __expf(s2.x - pm) * pr;
                As[pq + 17][prow] = __expf(s2.y - pm) * pr;
                As[pq + 18][prow] = __expf(s2.z - pm) * pr;
                As[pq + 19][prow] = __expf(s2.w - pm) * pr;
            }
        }
        // V tile: SB x HDv
        if (HDv == 64) {  // SB == 32
            int vrow = tid >> 4, vq = (tid & 15) << 2;
#pragma unroll
            for (int rr = 0; rr < 2; rr++) {
                int r = vrow + rr * 16;
                float4 v = *(const float4*)(V + (long long)(s0 + r) * vrs + h * HDv + vq);
                Bs[r][vq + 0] = v.x; Bs[r][vq + 1] = v.y;
                Bs[r][vq + 2] = v.z; Bs[r][vq + 3] = v.w;
            }
        } else {          // HDv == 128, SB == 16
            int vrow = tid >> 5, vq = (tid & 31) << 2;
#pragma unroll
            for (int rr = 0; rr < 2; rr++) {
                int r = vrow + rr * 8;
                float4 v = *(const float4*)(V + (long long)(s0 + r) * vrs + h * HDv + vq);
                Bs[r][vq + 0] = v.x; Bs[r][vq + 1] = v.y;
                Bs[r][vq + 2] = v.z; Bs[r][vq + 3] = v.w;
            }
        }
        __syncthreads();
#pragma unroll
        for (int kk = 0; kk < SB; kk += 8) {
            unsigned afh[MT][4], afl[MT][4], bfh[4][2], bfl[4][2];
#pragma unroll
            for (int mt = 0; mt < MT; mt++) {
                int mb = mw + mt * 16 + g;
                split_tf32(As[kk + tig][mb],         afh[mt][0], afl[mt][0]);
                split_tf32(As[kk + tig][mb + 8],     afh[mt][1], afl[mt][1]);
                split_tf32(As[kk + tig + 4][mb],     afh[mt][2], afl[mt][2]);
                split_tf32(As[kk + tig + 4][mb + 8], afh[mt][3], afl[mt][3]);
            }
#pragma unroll
            for (int nt = 0; nt < 4; nt++) {
                int nb = nw + nt * 8 + g;
                split_tf32(Bs[kk + tig][nb],     bfh[nt][0], bfl[nt][0]);
                split_tf32(Bs[kk + tig + 4][nb], bfh[nt][1], bfl[nt][1]);
            }
#pragma unroll
            for (int mt = 0; mt < MT; mt++)
#pragma unroll
                for (int nt = 0; nt < 4; nt++) {
                    mma_tf32(acc[mt][nt], afl[mt], bfh[nt]);
                    mma_tf32(acc[mt][nt], afh[mt], bfl[nt]);
                    mma_tf32(acc[mt][nt], afh[mt], bfh[nt]);
                }
        }
        __syncthreads();
    }

#pragma unroll
    for (int mt = 0; mt < MT; mt++)
#pragma unroll
        for (int nt = 0; nt < 4; nt++) {
            int row = t0 + mw + mt * 16 + g;
            int col = h * HDv + nw + nt * 8 + 2 * tig;
            O[(long long)row * ors + col]           = acc[mt][nt][0];
            O[(long long)row * ors + col + 1]       = acc[mt][nt][1];
            O[(long long)(row + 8) * ors + col]     = acc[mt][nt][2];
            O[(long long)(row + 8) * ors + col + 1] = acc[mt][nt][3];
        }
}

// ---------------- combined slice j: out_j += c/16 * sum_{h<4} softmax(S)[h,t,s] ----------------
// c = sp[0] + sp[1] + sp[3]  (broadcast quirk: every slice gets the same scalar)
__global__ void __launch_bounds__(256) combined_add(
    long long sOff, long long statsOff,
    const float* __restrict__ sp, float* __restrict__ out, int accumulate) {
    int t0 = blockIdx.y * 64, s0 = blockIdx.x * 64;
    const float* stats = g_scratch + statsOff;
    __shared__ float smx[4][64], srd[4][64];
    int tid = threadIdx.x;
    {
        int hh = tid >> 6, t = tid & 63;
        smx[hh][t] = stats[((long long)hh * TT + t0 + t) * 2];
        srd[hh][t] = stats[((long long)hh * TT + t0 + t) * 2 + 1];
    }
    __syncthreads();
    int ty = tid >> 4, tx = tid & 15;
    float acc[4][4] = {};
    for (int h = 0; h < 4; h++) {
        const float* Sp = g_scratch + sOff + ((long long)h * TT + t0) * TT + s0;
#pragma unroll
        for (int i = 0; i < 4; i++) {
            int t = ty * 4 + i;
            float m = smx[h][t], r = srd[h][t];
            float4 sv = *(const float4*)(Sp + (long long)t * TT + tx * 4);
            acc[i][0] += __expf(sv.x - m) * r;
            acc[i][1] += __expf(sv.y - m) * r;
            acc[i][2] += __expf(sv.z - m) * r;
            acc[i][3] += __expf(sv.w - m) * r;
        }
    }
    float coeff = (sp[0] + sp[1] + sp[3]) * (1.0f / 16.0f);
#pragma unroll
    for (int i = 0; i < 4; i++)
#pragma unroll
        for (int j = 0; j < 4; j++) {
            long long o = (long long)(t0 + ty * 4 + i) * TT + s0 + tx * 4 + j;
            float v = coeff * acc[i][j];
            if (accumulate) v += out[o];
            out[o] = v;
        }
}

// ---------------- linear interpolation of g_small [256,1024] -> hier_in[:,1024:2048] ----------------
__global__ void interp_kernel(long long gsOff, long long hinOff) {
    const float* gsmall = g_scratch + gsOff;
    float* hin = g_scratch + hinOff;
    int idx = blockIdx.x * 256 + threadIdx.x;
    if (idx >= TT * DD) return;
    int t = idx >> 10, c = idx & 1023;
    float src = (t + 0.5f) * (256.0f / 2048.0f) - 0.5f;
    src = fminf(fmaxf(src, 0.0f), 255.0f);
    int i0 = (int)floorf(src);
    int i1 = min(i0 + 1, 255);
    float w = src - (float)i0;
    hin[(long long)t * 2048 + 1024 + c] = gsmall[i0 * 1024 + c] * (1.0f - w) + gsmall[i1 * 1024 + c] * w;
}

// ---------------- weighted = p0*lin + p1*sparse + p2*hier + p3*quantum ----------------
__global__ void weighted_kernel(const float* __restrict__ sp,
                                long long aOff, long long bOff, long long cOff, long long dOff,
                                float* __restrict__ out) {
    int idx = blockIdx.x * 256 + threadIdx.x;
    if (idx >= TT * DD) return;
    out[idx] = sp[0] * g_scratch[aOff + idx] + sp[1] * g_scratch[bOff + idx]
             + sp[2] * g_scratch[cOff + idx] + sp[3] * g_scratch[dOff + idx];
}

// ---------------- host launcher: kernel launches ONLY ----------------
extern "C" void kernel_launch(void* const* d_in, const int* in_sizes, int n_in,
                              void* d_out, int out_size) {
    const float* query = (const float*)d_in[0];
    const float* key   = (const float*)d_in[1];
    const float* value = (const float*)d_in[2];
    const float* sp    = (const float*)d_in[3];
    const float* Wqkv_lin = (const float*)d_in[4];
    const float* b_lin  = (const float*)d_in[5];
    const float* Wo_lin = (const float*)d_in[6];
    const float* bo_lin = (const float*)d_in[7];
    const float* spars  = (const float*)d_in[8];
    const float* Wqkv_loc = (const float*)d_in[9];
    const float* b_loc  = (const float*)d_in[10];
    const float* Wo_loc = (const float*)d_in[11];
    const float* bo_loc = (const float*)d_in[12];
    const float* Wqkv_glb = (const float*)d_in[13];
    const float* b_glb  = (const float*)d_in[14];
    const float* Wo_glb = (const float*)d_in[15];
    const float* bo_glb = (const float*)d_in[16];
    const float* Wf = (const float*)d_in[17];
    const float* bf = (const float*)d_in[18];
    const float* Rq = (const float*)d_in[19];
    const float* ent = (const float*)d_in[20];

    float* out = (float*)d_out;
    float* comb0 = out + (size_t)TT * DD;       // linear_w
    float* comb1 = comb0 + (size_t)TT * TT;     // sparse_w
    float* comb2 = comb1 + (size_t)TT * TT;     // quantum_w

    const long long TT2 = (long long)TT * TT;

    prep_kernel<<<256, 256>>>(Rq, spars, ent);

    dim3 gProj(16, 16, 1);       // N/64=16, M/128=16
    dim3 gScores4(32, 16, 4);    // N/64=32, M/128=16, 4 heads
    dim3 gComb(32, 32);

    // ===== Linear MHA (4 head-groups of 4) =====
    gemm_tf32<<<gProj, 256>>>(query, 0, 0, DD, Wqkv_lin, 0, 0, DD, b_lin, -1, OFF_Q, 0, DD, TT, DD, DD);
    gemm_tf32<<<gProj, 256>>>(key,   0, 0, DD, Wqkv_lin + DD * DD, 0, 0, DD, b_lin + DD, -1, OFF_K, 0, DD, TT, DD, DD);
    gemm_tf32<<<gProj, 256>>>(value, 0, 0, DD, Wqkv_lin + 2 * DD * DD, 0, 0, DD, b_lin + 2 * DD, -1, OFF_V, 0, DD, TT, DD, DD);
    for (int g = 0; g < 4; g++) {
        long long ho = (long long)g * 256;   // 4 heads * 64 dims
        gemm_tf32<<<gScores4, 256>>>(nullptr, OFF_Q + ho, 64, DD, nullptr, OFF_K + ho, 64, DD, nullptr, OFF_SCALES + g * 4, OFF_S, TT2, TT, TT, TT, 64);
        stats_kernel<<<dim3(TT, 4), 256>>>(OFF_S, OFF_STATS, TT);
        av_tf32<64, 32><<<dim3(32, 4), 256>>>(OFF_S, OFF_STATS, nullptr, OFF_V + ho, DD, OFF_AO + ho, DD, TT);
        combined_add<<<gComb, 256>>>(OFF_S, OFF_STATS, sp, comb0, g == 0 ? 0 : 1);
    }
    gemm_tf32<<<gProj, 256>>>(nullptr, OFF_AO, 0, DD, Wo_lin, 0, 0, DD, bo_lin, -1, OFF_LIN, 0, DD, TT, DD, DD);

    // ===== Sparse (raw heads, masked scale) =====
    for (int g = 0; g < 4; g++) {
        long long ho = (long long)g * 256;
        gemm_tf32<<<gScores4, 256>>>(query + ho, 0, 64, DD, key + ho, 0, 64, DD, nullptr, OFF_SCALES + 16 + g * 4, OFF_S, TT2, TT, TT, TT, 64);
        stats_kernel<<<dim3(TT, 4), 256>>>(OFF_S, OFF_STATS, TT);
        av_tf32<64, 32><<<dim3(32, 4), 256>>>(OFF_S, OFF_STATS, value + ho, 0, DD, OFF_SP + ho, DD, TT);
        combined_add<<<gComb, 256>>>(OFF_S, OFF_STATS, sp, comb1, g == 0 ? 0 : 1);
    }

    // ===== Quantum (rotated heads, gated scale) =====
    gemm_tf32<<<dim3(1, 16, 16), 256>>>(query, 0, 64, DD, nullptr, OFF_RT, 4096, 64, nullptr, -1, OFF_Q, 64, DD, TT, 64, 64);
    gemm_tf32<<<dim3(1, 16, 16), 256>>>(key,   0, 64, DD, nullptr, OFF_RT, 4096, 64, nullptr, -1, OFF_K, 64, DD, TT, 64, 64);
    for (int g = 0; g < 4; g++) {
        long long ho = (long long)g * 256;
        gemm_tf32<<<gScores4, 256>>>(nullptr, OFF_Q + ho, 64, DD, nullptr, OFF_K + ho, 64, DD, nullptr, OFF_SCALES + 32 + g * 4, OFF_S, TT2, TT, TT, TT, 64);
        stats_kernel<<<dim3(TT, 4), 256>>>(OFF_S, OFF_STATS, TT);
        av_tf32<64, 32><<<dim3(32, 4), 256>>>(OFF_S, OFF_STATS, value + ho, 0, DD, OFF_QT + ho, DD, TT);
        combined_add<<<gComb, 256>>>(OFF_S, OFF_STATS, sp, comb2, g == 0 ? 0 : 1);
    }

    // ===== Local MHA (8 heads of 128, 2 groups of 4) =====
    gemm_tf32<<<gProj, 256>>>(query, 0, 0, DD, Wqkv_loc, 0, 0, DD, b_loc, -1, OFF_Q, 0, DD, TT, DD, DD);
    gemm_tf32<<<gProj, 256>>>(key,   0, 0, DD, Wqkv_loc + DD * DD, 0, 0, DD, b_loc + DD, -1, OFF_K, 0, DD, TT, DD, DD);
    gemm_tf32<<<gProj, 256>>>(value, 0, 0, DD, Wqkv_loc + 2 * DD * DD, 0, 0, DD, b_loc + 2 * DD, -1, OFF_V, 0, DD, TT, DD, DD);
    for (int g = 0; g < 2; g++) {
        long long ho = (long long)g * 512;   // 4 heads * 128 dims
        gemm_tf32<<<gScores4, 256>>>(nullptr, OFF_Q + ho, 128, DD, nullptr, OFF_K + ho, 128, DD, nullptr, OFF_SCALES + 48 + g * 4, OFF_S, TT2, TT, TT, TT, 128);
        stats_kernel<<<dim3(TT, 4), 256>>>(OFF_S, OFF_STATS, TT);
        av_tf32<128, 16><<<dim3(32, 4), 256>>>(OFF_S, OFF_STATS, nullptr, OFF_V + ho, DD, OFF_AO + ho, DD, TT);
    }
    gemm_tf32<<<gProj, 256>>>(nullptr, OFF_AO, 0, DD, Wo_loc, 0, 0, DD, bo_loc, -1, OFF_HIN, 0, 2048, TT, DD, DD);

    // ===== Global MHA (subsampled tokens stride 8, 8 heads of 128) =====
    dim3 gProjG(16, 2, 1);  // M=256 -> 2 blocks of 128
    gemm_tf32<<<gProjG, 256>>>(query, 0, 0, 8 * DD, Wqkv_glb, 0, 0, DD, b_glb, -1, OFF_GQ, 0, DD, TG, DD, DD);
    gemm_tf32<<<gProjG, 256>>>(key,   0, 0, 8 * DD, Wqkv_glb + DD * DD, 0, 0, DD, b_glb + DD, -1, OFF_GK, 0, DD, TG, DD, DD);
    gemm_tf32<<<gProjG, 256>>>(value, 0, 0, 8 * DD, Wqkv_glb + 2 * DD * DD, 0, 0, DD, b_glb + 2 * DD, -1, OFF_GV, 0, DD, TG, DD, DD);
    gemm_tf32<<<dim3(4, 2, 8), 256>>>(nullptr, OFF_GQ, 128, DD, nullptr, OFF_GK, 128, DD, nullptr, OFF_SCALES + 48, OFF_S, (long long)TG * TG, TG, TG, TG, 128);
    stats_kernel<<<dim3(TG, 8), 256>>>(OFF_S, OFF_STATS, TG);
    av_tf32<128, 16><<<dim3(4, 8), 256>>>(OFF_S, OFF_STATS, nullptr, OFF_GV, DD, OFF_GAO, DD, TG);
    gemm_tf32<<<gProjG, 256>>>(nullptr, OFF_GAO, 0, DD, Wo_glb, 0, 0, DD, bo_glb, -1, OFF_GSM, 0, DD, TG, DD, DD);
    interp_kernel<<<(TT * DD + 255) / 256, 256>>>(OFF_GSM, OFF_HIN);

    // ===== Hierarchical fuse: [local|global] @ Wf^T + bf =====
    gemm_tf32<<<gProj, 256>>>(nullptr, OFF_HIN, 0, 2048, Wf, 0, 0, 2048, bf, -1, OFF_HOUT, 0, DD, TT, DD, 2048);

    // ===== Weighted combination =====
    weighted_kernel<<<(TT * DD + 255) / 256, 256>>>(sp, OFF_LIN, OFF_SP, OFF_HOUT, OFF_QT, out);
}